// round 1
// baseline (speedup 1.0000x reference)
#include <cuda_runtime.h>
#include <math.h>

// Problem constants (fixed shapes for EPSparseMoeBlock_12300786335900)
#define T_TOK 4096   // B*L tokens
#define DDIM  2048   // hidden dim
#define NEXP  8      // experts
#define IMOE  768    // expert intermediate
#define ISH   4096   // shared expert intermediate

// ---------------- device scratch (static, no allocations) ----------------
__device__ float g_act_shared[(size_t)T_TOK * ISH];          // 64 MB: silu(g)*u shared
__device__ float g_act_moe[(size_t)NEXP * T_TOK * IMOE];     // 100 MB: silu(g)*u per (e,slot)
__device__ int   g_idx[NEXP * T_TOK];                        // token id per (e,slot)
__device__ float g_cw[NEXP * T_TOK];                         // combine weight per (e,slot)
__device__ int   g_cnt[NEXP];                                // tokens per expert
__device__ float g_sgate[T_TOK];                             // sigmoid shared-expert gate

// ---------------- small kernels ----------------
__global__ void zero_cnt_kernel() {
    if (threadIdx.x < NEXP) g_cnt[threadIdx.x] = 0;
}

// Router: per-token 9 dot products (8 expert logits + shared gate logit),
// top-2 selection with renormalized weights (== softmax over the 2 top logits),
// atomic scatter into per-expert token lists.
__global__ void router_kernel(const float* __restrict__ h,
                              const float* __restrict__ gate_w,
                              const float* __restrict__ seg_w) {
    int t = blockIdx.x;
    int tid = threadIdx.x;               // 128 threads
    float acc[9];
#pragma unroll
    for (int e = 0; e < 9; e++) acc[e] = 0.f;
    const float* hp = h + (size_t)t * DDIM;
    for (int d = tid; d < DDIM; d += 128) {
        float hv = hp[d];
#pragma unroll
        for (int e = 0; e < 8; e++) acc[e] += hv * gate_w[e * DDIM + d];
        acc[8] += hv * seg_w[d];
    }
#pragma unroll
    for (int e = 0; e < 9; e++) {
#pragma unroll
        for (int off = 16; off > 0; off >>= 1)
            acc[e] += __shfl_down_sync(0xffffffffu, acc[e], off);
    }
    __shared__ float s[9][4];
    int warp = tid >> 5, lane = tid & 31;
    if (lane == 0) {
#pragma unroll
        for (int e = 0; e < 9; e++) s[e][warp] = acc[e];
    }
    __syncthreads();
    if (tid == 0) {
        float logits[9];
#pragma unroll
        for (int e = 0; e < 9; e++)
            logits[e] = s[e][0] + s[e][1] + s[e][2] + s[e][3];
        int i1 = 0; float l1 = logits[0];
#pragma unroll
        for (int e = 1; e < 8; e++)
            if (logits[e] > l1) { l1 = logits[e]; i1 = e; }
        int i2 = -1; float l2 = -3.0e38f;
#pragma unroll
        for (int e = 0; e < 8; e++)
            if (e != i1 && logits[e] > l2) { l2 = logits[e]; i2 = e; }
        // renormalized top-2 softmax weights
        float w1 = 1.f / (1.f + expf(l2 - l1));
        float w2 = 1.f - w1;
        int r1 = atomicAdd(&g_cnt[i1], 1);
        g_idx[i1 * T_TOK + r1] = t;  g_cw[i1 * T_TOK + r1] = w1;
        int r2 = atomicAdd(&g_cnt[i2], 1);
        g_idx[i2 * T_TOK + r2] = t;  g_cw[i2 * T_TOK + r2] = w2;
        g_sgate[t] = 1.f / (1.f + expf(-logits[8]));
    }
}

__device__ __forceinline__ float silu_f(float x) {
    return x / (1.f + expf(-x));
}

// ---------------- fused gate/up GEMM: act = silu(A@Bg^T) * (A@Bu^T) ----------------
// A row-major [*, Kd]; Bg/Bu row-major [N, Kd]; 128x128x8 tile, 256 thr, 8x8/thread.
// GATHER=true: A rows are gathered tokens (expert blockIdx.z), output -> g_act_moe.
// GATHER=false: A rows are tokens directly, output -> g_act_shared.
template<bool GATHER>
__global__ __launch_bounds__(256, 1)
void gemm_gateup(const float* __restrict__ A, int lda,
                 const float* __restrict__ Bg_base,
                 const float* __restrict__ Bu_base,
                 long long strideB, int Kd)
{
    const int BM = 128, BN = 128, BK = 8;
    int e = blockIdx.z;
    int M = GATHER ? g_cnt[e] : T_TOK;
    int m0 = blockIdx.y * BM;
    if (m0 >= M) return;
    int n0 = blockIdx.x * BN;

    const float* Bg = Bg_base + (long long)e * strideB;
    const float* Bu = Bu_base + (long long)e * strideB;
    const int* idx = GATHER ? (g_idx + e * T_TOK) : nullptr;
    float* C;
    int ldc;
    if (GATHER) { C = g_act_moe + (long long)e * T_TOK * IMOE; ldc = IMOE; }
    else        { C = g_act_shared;                            ldc = ISH;  }

    __shared__ float As [BK][BM];
    __shared__ float Bsg[BK][BN];
    __shared__ float Bsu[BK][BN];

    int tid = threadIdx.x;
    int ty = tid >> 4, tx = tid & 15;
    int lrow = tid >> 1;             // 0..127
    int lcol = (tid & 1) * 4;        // 0 or 4

    const float* arow;
    bool avalid = true;
    if (GATHER) {
        int r = m0 + lrow;
        if (r < M) arow = A + (long long)idx[r] * lda;
        else { avalid = false; arow = A; }
    } else {
        arow = A + (long long)(m0 + lrow) * lda;
    }
    const float* bgrow = Bg + (long long)(n0 + lrow) * Kd;
    const float* burow = Bu + (long long)(n0 + lrow) * Kd;

    float accg[8][8], accu[8][8];
#pragma unroll
    for (int i = 0; i < 8; i++)
#pragma unroll
        for (int j = 0; j < 8; j++) { accg[i][j] = 0.f; accu[i][j] = 0.f; }

    for (int k0 = 0; k0 < Kd; k0 += BK) {
        float4 av  = avalid ? *(const float4*)(arow + k0 + lcol)
                            : make_float4(0.f, 0.f, 0.f, 0.f);
        float4 bgv = *(const float4*)(bgrow + k0 + lcol);
        float4 buv = *(const float4*)(burow + k0 + lcol);
        As [lcol + 0][lrow] = av.x;  As [lcol + 1][lrow] = av.y;
        As [lcol + 2][lrow] = av.z;  As [lcol + 3][lrow] = av.w;
        Bsg[lcol + 0][lrow] = bgv.x; Bsg[lcol + 1][lrow] = bgv.y;
        Bsg[lcol + 2][lrow] = bgv.z; Bsg[lcol + 3][lrow] = bgv.w;
        Bsu[lcol + 0][lrow] = buv.x; Bsu[lcol + 1][lrow] = buv.y;
        Bsu[lcol + 2][lrow] = buv.z; Bsu[lcol + 3][lrow] = buv.w;
        __syncthreads();
#pragma unroll
        for (int k = 0; k < BK; k++) {
            float4 a0 = *(const float4*)&As [k][ty * 8];
            float4 a1 = *(const float4*)&As [k][ty * 8 + 4];
            float4 g0 = *(const float4*)&Bsg[k][tx * 8];
            float4 g1 = *(const float4*)&Bsg[k][tx * 8 + 4];
            float4 u0 = *(const float4*)&Bsu[k][tx * 8];
            float4 u1 = *(const float4*)&Bsu[k][tx * 8 + 4];
            float rm[8] = {a0.x, a0.y, a0.z, a0.w, a1.x, a1.y, a1.z, a1.w};
            float rg[8] = {g0.x, g0.y, g0.z, g0.w, g1.x, g1.y, g1.z, g1.w};
            float ru[8] = {u0.x, u0.y, u0.z, u0.w, u1.x, u1.y, u1.z, u1.w};
#pragma unroll
            for (int i = 0; i < 8; i++)
#pragma unroll
                for (int j = 0; j < 8; j++) {
                    accg[i][j] += rm[i] * rg[j];
                    accu[i][j] += rm[i] * ru[j];
                }
        }
        __syncthreads();
    }

#pragma unroll
    for (int i = 0; i < 8; i++) {
        int r = m0 + ty * 8 + i;
        if (GATHER && r >= M) continue;
        float* crow = C + (long long)r * ldc + n0 + tx * 8;
#pragma unroll
        for (int j = 0; j < 8; j++)
            crow[j] = silu_f(accg[i][j]) * accu[i][j];
    }
}

// ---------------- down GEMM ----------------
// MOE=true : out[token] += cw * (act_moe[e] @ down_proj[e]^T)   (atomicAdd)
// MOE=false: out[t]      = sgate[t] * (act_shared @ shared_down^T) (plain store)
template<bool MOE>
__global__ __launch_bounds__(256, 1)
void gemm_down(const float* __restrict__ Bbase, long long strideB,
               float* __restrict__ out, int Kd)
{
    const int BM = 128, BN = 128, BK = 8;
    int e = blockIdx.z;
    int M = MOE ? g_cnt[e] : T_TOK;
    int m0 = blockIdx.y * BM;
    if (m0 >= M) return;
    int n0 = blockIdx.x * BN;

    const float* A; int lda;
    if (MOE) { A = g_act_moe + (long long)e * T_TOK * IMOE; lda = IMOE; }
    else     { A = g_act_shared;                            lda = ISH;  }
    const float* B = Bbase + (long long)e * strideB;

    __shared__ float As[BK][BM];
    __shared__ float Bs[BK][BN];

    int tid = threadIdx.x;
    int ty = tid >> 4, tx = tid & 15;
    int lrow = tid >> 1;
    int lcol = (tid & 1) * 4;

    const float* arow;
    bool avalid = true;
    if (MOE) {
        int r = m0 + lrow;
        if (r < M) arow = A + (long long)r * lda;
        else { avalid = false; arow = A; }
    } else {
        arow = A + (long long)(m0 + lrow) * lda;
    }
    const float* brow = B + (long long)(n0 + lrow) * Kd;

    float acc[8][8];
#pragma unroll
    for (int i = 0; i < 8; i++)
#pragma unroll
        for (int j = 0; j < 8; j++) acc[i][j] = 0.f;

    for (int k0 = 0; k0 < Kd; k0 += BK) {
        float4 av = avalid ? *(const float4*)(arow + k0 + lcol)
                           : make_float4(0.f, 0.f, 0.f, 0.f);
        float4 bv = *(const float4*)(brow + k0 + lcol);
        As[lcol + 0][lrow] = av.x; As[lcol + 1][lrow] = av.y;
        As[lcol + 2][lrow] = av.z; As[lcol + 3][lrow] = av.w;
        Bs[lcol + 0][lrow] = bv.x; Bs[lcol + 1][lrow] = bv.y;
        Bs[lcol + 2][lrow] = bv.z; Bs[lcol + 3][lrow] = bv.w;
        __syncthreads();
#pragma unroll
        for (int k = 0; k < BK; k++) {
            float4 a0 = *(const float4*)&As[k][ty * 8];
            float4 a1 = *(const float4*)&As[k][ty * 8 + 4];
            float4 b0 = *(const float4*)&Bs[k][tx * 8];
            float4 b1 = *(const float4*)&Bs[k][tx * 8 + 4];
            float rm[8] = {a0.x, a0.y, a0.z, a0.w, a1.x, a1.y, a1.z, a1.w};
            float rn[8] = {b0.x, b0.y, b0.z, b0.w, b1.x, b1.y, b1.z, b1.w};
#pragma unroll
            for (int i = 0; i < 8; i++)
#pragma unroll
                for (int j = 0; j < 8; j++)
                    acc[i][j] += rm[i] * rn[j];
        }
        __syncthreads();
    }

    if (MOE) {
#pragma unroll
        for (int i = 0; i < 8; i++) {
            int r = m0 + ty * 8 + i;
            if (r >= M) continue;
            int tok = g_idx[e * T_TOK + r];
            float w = g_cw[e * T_TOK + r];
            float* orow = out + (long long)tok * DDIM + n0 + tx * 8;
#pragma unroll
            for (int j = 0; j < 8; j++)
                atomicAdd(&orow[j], w * acc[i][j]);
        }
    } else {
#pragma unroll
        for (int i = 0; i < 8; i++) {
            int r = m0 + ty * 8 + i;
            float s = g_sgate[r];
            float* orow = out + (long long)r * DDIM + n0 + tx * 8;
            float4 v0 = make_float4(s * acc[i][0], s * acc[i][1],
                                    s * acc[i][2], s * acc[i][3]);
            float4 v1 = make_float4(s * acc[i][4], s * acc[i][5],
                                    s * acc[i][6], s * acc[i][7]);
            *(float4*)&orow[0] = v0;
            *(float4*)&orow[4] = v1;
        }
    }
}

// ---------------- launch ----------------
extern "C" void kernel_launch(void* const* d_in, const int* in_sizes, int n_in,
                              void* d_out, int out_size) {
    const float* h    = (const float*)d_in[0];  // [T, D]
    const float* gw   = (const float*)d_in[1];  // [E, D]
    const float* gup  = (const float*)d_in[2];  // [E, 2I, D]
    const float* dwn  = (const float*)d_in[3];  // [E, D, I]
    const float* sgw  = (const float*)d_in[4];  // [IS, D]
    const float* suw  = (const float*)d_in[5];  // [IS, D]
    const float* sdw  = (const float*)d_in[6];  // [D, IS]
    const float* segw = (const float*)d_in[7];  // [1, D]
    float* out = (float*)d_out;

    // 1) reset per-expert counters (graph replays must be self-contained)
    zero_cnt_kernel<<<1, 32>>>();

    // 2) router: top-2 dispatch + sigmoid shared gate
    router_kernel<<<T_TOK, 128>>>(h, gw, segw);

    // 3) MoE gate/up (gathered): act_moe[e,r,:] = silu(h_tok @ Wg_e^T) * (h_tok @ Wu_e^T)
    gemm_gateup<true><<<dim3(IMOE / 128, T_TOK / 128, NEXP), 256>>>(
        h, DDIM,
        gup,                                // gate rows (first I rows of 2I)
        gup + (long long)IMOE * DDIM,       // up rows
        (long long)2 * IMOE * DDIM, DDIM);

    // 4) shared gate/up: act_shared = silu(h @ Wg^T) * (h @ Wu^T)
    gemm_gateup<false><<<dim3(ISH / 128, T_TOK / 128, 1), 256>>>(
        h, DDIM, sgw, suw, 0LL, DDIM);

    // 5) shared down: out = sgate * (act_shared @ Wd^T)   (covers every output element)
    gemm_down<false><<<dim3(DDIM / 128, T_TOK / 128, 1), 256>>>(
        sdw, 0LL, out, ISH);

    // 6) MoE down: out[token] += cw * (act_moe[e] @ down_e^T)
    gemm_down<true><<<dim3(DDIM / 128, T_TOK / 128, NEXP), 256>>>(
        dwn, (long long)DDIM * IMOE, out, IMOE);
}

// round 2
// speedup vs baseline: 3.5877x; 3.5877x over previous
#include <cuda_runtime.h>
#include <math.h>

#define T_TOK 4096   // B*L tokens
#define DDIM  2048   // hidden dim
#define NEXP  8      // experts
#define IMOE  768    // expert intermediate
#define ISH   4096   // shared expert intermediate

// ---------------- device scratch (static, no allocations) ----------------
__device__ float g_act_shared[(size_t)T_TOK * ISH];
__device__ float g_act_moe[(size_t)NEXP * T_TOK * IMOE];
__device__ int   g_idx[NEXP * T_TOK];
__device__ float g_cw[NEXP * T_TOK];
__device__ int   g_cnt[NEXP];
__device__ float g_sgate[T_TOK];

// ---------------- small kernels ----------------
__global__ void zero_cnt_kernel() {
    if (threadIdx.x < NEXP) g_cnt[threadIdx.x] = 0;
}

__global__ void router_kernel(const float* __restrict__ h,
                              const float* __restrict__ gate_w,
                              const float* __restrict__ seg_w) {
    int t = blockIdx.x;
    int tid = threadIdx.x;               // 128 threads
    float acc[9];
#pragma unroll
    for (int e = 0; e < 9; e++) acc[e] = 0.f;
    const float* hp = h + (size_t)t * DDIM;
    for (int d = tid; d < DDIM; d += 128) {
        float hv = hp[d];
#pragma unroll
        for (int e = 0; e < 8; e++) acc[e] += hv * gate_w[e * DDIM + d];
        acc[8] += hv * seg_w[d];
    }
#pragma unroll
    for (int e = 0; e < 9; e++) {
#pragma unroll
        for (int off = 16; off > 0; off >>= 1)
            acc[e] += __shfl_down_sync(0xffffffffu, acc[e], off);
    }
    __shared__ float s[9][4];
    int warp = tid >> 5, lane = tid & 31;
    if (lane == 0) {
#pragma unroll
        for (int e = 0; e < 9; e++) s[e][warp] = acc[e];
    }
    __syncthreads();
    if (tid == 0) {
        float logits[9];
#pragma unroll
        for (int e = 0; e < 9; e++)
            logits[e] = s[e][0] + s[e][1] + s[e][2] + s[e][3];
        int i1 = 0; float l1 = logits[0];
#pragma unroll
        for (int e = 1; e < 8; e++)
            if (logits[e] > l1) { l1 = logits[e]; i1 = e; }
        int i2 = -1; float l2 = -3.0e38f;
#pragma unroll
        for (int e = 0; e < 8; e++)
            if (e != i1 && logits[e] > l2) { l2 = logits[e]; i2 = e; }
        float w1 = 1.f / (1.f + expf(l2 - l1));
        float w2 = 1.f - w1;
        int r1 = atomicAdd(&g_cnt[i1], 1);
        g_idx[i1 * T_TOK + r1] = t;  g_cw[i1 * T_TOK + r1] = w1;
        int r2 = atomicAdd(&g_cnt[i2], 1);
        g_idx[i2 * T_TOK + r2] = t;  g_cw[i2 * T_TOK + r2] = w2;
        g_sgate[t] = 1.f / (1.f + expf(-logits[8]));
    }
}

__device__ __forceinline__ float silu_f(float x) {
    return x / (1.f + expf(-x));
}

// ---------------- tf32 mma building blocks ----------------
__device__ __forceinline__ unsigned f2tf(float x) {
    unsigned u;
    asm("cvt.rna.tf32.f32 %0, %1;" : "=r"(u) : "f"(x));
    return u;
}

__device__ __forceinline__ void ldsm4(unsigned& r0, unsigned& r1,
                                      unsigned& r2, unsigned& r3, unsigned addr) {
    asm volatile("ldmatrix.sync.aligned.m8n8.x4.shared.b16 {%0,%1,%2,%3}, [%4];"
                 : "=r"(r0), "=r"(r1), "=r"(r2), "=r"(r3) : "r"(addr));
}

__device__ __forceinline__ void mma8(float* c, const unsigned* a, const unsigned* b) {
    asm volatile("mma.sync.aligned.m16n8k8.row.col.f32.tf32.tf32.f32 "
                 "{%0,%1,%2,%3}, {%4,%5,%6,%7}, {%8,%9}, {%0,%1,%2,%3};"
                 : "+f"(c[0]), "+f"(c[1]), "+f"(c[2]), "+f"(c[3])
                 : "r"(a[0]), "r"(a[1]), "r"(a[2]), "r"(a[3]),
                   "r"(b[0]), "r"(b[1]));
}

// XOR-swizzled 16B-chunk index for a [rows x 32-float] tile (8 chunks/row)
__device__ __forceinline__ int swz(int row, int chunk) {
    return row * 8 + (chunk ^ (row & 7));
}

// ============= fused gate/up GEMM (tf32 tensor cores) =============
// Block: 128 M x 64 N (for BOTH gate and up matrices).
// Warps 4(M) x 2(N): warp tile 32x32 per matrix.
// act[r][n] = silu(A@Bg^T) * (A@Bu^T)
template<bool GATHER>
__global__ void __launch_bounds__(256, 1)
gemm_gateup_t(const float* __restrict__ A,
              const float* __restrict__ Bg_base,
              const float* __restrict__ Bu_base,
              long long strideB, int Kd)
{
    extern __shared__ unsigned smem[];
    const int e  = blockIdx.z;
    const int M  = GATHER ? g_cnt[e] : T_TOK;
    const int m0 = blockIdx.y * 128;
    if (m0 >= M) return;
    const int n0 = blockIdx.x * 64;

    const float* Bg = Bg_base + (long long)e * strideB;
    const float* Bu = Bu_base + (long long)e * strideB;
    float* C; int ldc;
    if (GATHER) { C = g_act_moe + (long long)e * T_TOK * IMOE; ldc = IMOE; }
    else        { C = g_act_shared;                            ldc = ISH;  }

    unsigned* sA = smem;           // 2 x 4096 u32
    unsigned* sG = smem + 8192;    // 2 x 2048 u32
    unsigned* sU = smem + 12288;   // 2 x 2048 u32

    const int tid  = threadIdx.x;
    const int lane = tid & 31, wid = tid >> 5;
    const int wm = (wid & 3) * 32;   // warp row base in block
    const int wn = (wid >> 2) * 32;  // warp col base in block (per matrix)
    const int ac = tid & 7;          // this thread's 16B chunk within k-tile

    // global load assignments (row-major, float4 granularity)
    const float* aptr[4]; bool aval[4]; int arow_[4];
#pragma unroll
    for (int i = 0; i < 4; i++) {
        int id = tid + i * 256; int row = id >> 3;
        arow_[i] = row;
        int r = m0 + row;
        if (GATHER) {
            aval[i] = (r < M);
            aptr[i] = aval[i] ? (A + (size_t)g_idx[e * T_TOK + r] * Kd + (id & 7) * 4)
                              : A;
        } else { aval[i] = true; aptr[i] = A + (size_t)r * Kd + (id & 7) * 4; }
    }
    const float* gptr[2]; const float* uptr[2]; int brow_[2];
#pragma unroll
    for (int i = 0; i < 2; i++) {
        int id = tid + i * 256; int row = id >> 3;
        brow_[i] = row;
        gptr[i] = Bg + (size_t)(n0 + row) * Kd + (id & 7) * 4;
        uptr[i] = Bu + (size_t)(n0 + row) * Kd + (id & 7) * 4;
    }

    float4 ra[4], rg[2], ru[2];
#pragma unroll
    for (int i = 0; i < 4; i++)
        ra[i] = aval[i] ? *(const float4*)(aptr[i]) : make_float4(0.f,0.f,0.f,0.f);
#pragma unroll
    for (int i = 0; i < 2; i++) { rg[i] = *(const float4*)(gptr[i]); ru[i] = *(const float4*)(uptr[i]); }

    auto stage_store = [&](int b) {
#pragma unroll
        for (int i = 0; i < 4; i++) {
            uint4 q = make_uint4(f2tf(ra[i].x), f2tf(ra[i].y), f2tf(ra[i].z), f2tf(ra[i].w));
            *(uint4*)(sA + b * 4096 + swz(arow_[i], ac) * 4) = q;
        }
#pragma unroll
        for (int i = 0; i < 2; i++) {
            uint4 qg = make_uint4(f2tf(rg[i].x), f2tf(rg[i].y), f2tf(rg[i].z), f2tf(rg[i].w));
            *(uint4*)(sG + b * 2048 + swz(brow_[i], ac) * 4) = qg;
            uint4 qu = make_uint4(f2tf(ru[i].x), f2tf(ru[i].y), f2tf(ru[i].z), f2tf(ru[i].w));
            *(uint4*)(sU + b * 2048 + swz(brow_[i], ac) * 4) = qu;
        }
    };
    stage_store(0);
    __syncthreads();

    float cg[2][4][4] = {}, cu[2][4][4] = {};
    const int S   = Kd / 32;
    const int sub = lane >> 3, rr = lane & 7;

    for (int s = 0; s < S; s++) {
        if (s + 1 < S) {
#pragma unroll
            for (int i = 0; i < 4; i++)
                ra[i] = aval[i] ? *(const float4*)(aptr[i] + (s + 1) * 32)
                                : make_float4(0.f,0.f,0.f,0.f);
#pragma unroll
            for (int i = 0; i < 2; i++) {
                rg[i] = *(const float4*)(gptr[i] + (s + 1) * 32);
                ru[i] = *(const float4*)(uptr[i] + (s + 1) * 32);
            }
        }
        const unsigned* tA = sA + (s & 1) * 4096;
        const unsigned* tG = sG + (s & 1) * 2048;
        const unsigned* tU = sU + (s & 1) * 2048;
#pragma unroll
        for (int ks = 0; ks < 4; ks++) {
            unsigned a[2][4], bg[4][2], bu[4][2];
#pragma unroll
            for (int mt = 0; mt < 2; mt++) {
                int row = wm + mt * 16 + (sub & 1) * 8 + rr;
                int chunk = 2 * ks + (sub >> 1);
                unsigned addr = (unsigned)__cvta_generic_to_shared(tA + swz(row, chunk) * 4);
                ldsm4(a[mt][0], a[mt][1], a[mt][2], a[mt][3], addr);
            }
#pragma unroll
            for (int j = 0; j < 4; j += 2) {
                int row = wn + (j + (sub >> 1)) * 8 + rr;
                int chunk = 2 * ks + (sub & 1);
                unsigned ag = (unsigned)__cvta_generic_to_shared(tG + swz(row, chunk) * 4);
                ldsm4(bg[j][0], bg[j][1], bg[j + 1][0], bg[j + 1][1], ag);
                unsigned au = (unsigned)__cvta_generic_to_shared(tU + swz(row, chunk) * 4);
                ldsm4(bu[j][0], bu[j][1], bu[j + 1][0], bu[j + 1][1], au);
            }
#pragma unroll
            for (int mt = 0; mt < 2; mt++)
#pragma unroll
                for (int nt = 0; nt < 4; nt++) {
                    mma8(cg[mt][nt], a[mt], bg[nt]);
                    mma8(cu[mt][nt], a[mt], bu[nt]);
                }
        }
        if (s + 1 < S) stage_store((s + 1) & 1);
        __syncthreads();
    }

    // epilogue: silu(g)*u
    const int rr2 = lane >> 2, cc = (lane & 3) * 2;
#pragma unroll
    for (int mt = 0; mt < 2; mt++) {
#pragma unroll
        for (int h = 0; h < 2; h++) {
            int r = m0 + wm + mt * 16 + rr2 + h * 8;
            if (GATHER && r >= M) continue;
            float* crow = C + (size_t)r * ldc + n0 + wn;
#pragma unroll
            for (int nt = 0; nt < 4; nt++) {
                float g0 = cg[mt][nt][2 * h + 0], g1 = cg[mt][nt][2 * h + 1];
                float u0 = cu[mt][nt][2 * h + 0], u1 = cu[mt][nt][2 * h + 1];
                float2 v = make_float2(silu_f(g0) * u0, silu_f(g1) * u1);
                *(float2*)(crow + nt * 8 + cc) = v;
            }
        }
    }
}

// ============= down GEMM (tf32 tensor cores) =============
// Block: 128 M x 128 N. Warps 4(M) x 2(N): warp tile 32x64.
// MOE=true : out[token] += cw * (act_moe[e] @ down_e^T)   (atomicAdd)
// MOE=false: out[t]      = sgate[t] * (act_shared @ Wd^T)
template<bool MOE>
__global__ void __launch_bounds__(256, 1)
gemm_down_t(const float* __restrict__ Bbase, long long strideB,
            float* __restrict__ out, int Kd)
{
    extern __shared__ unsigned smem[];
    const int e  = blockIdx.z;
    const int M  = MOE ? g_cnt[e] : T_TOK;
    const int m0 = blockIdx.y * 128;
    if (m0 >= M) return;
    const int n0 = blockIdx.x * 128;

    const float* A; int lda;
    if (MOE) { A = g_act_moe + (size_t)e * T_TOK * IMOE; lda = IMOE; }
    else     { A = g_act_shared;                         lda = ISH;  }
    const float* B = Bbase + (long long)e * strideB;

    unsigned* sA = smem;          // 2 x 4096
    unsigned* sB = smem + 8192;   // 2 x 4096

    const int tid  = threadIdx.x;
    const int lane = tid & 31, wid = tid >> 5;
    const int wm = (wid & 3) * 32;
    const int wn = (wid >> 2) * 64;
    const int ac = tid & 7;

    const float* aptr[4]; bool aval[4]; int arow_[4];
    const float* bptr[4]; int brow_[4];
#pragma unroll
    for (int i = 0; i < 4; i++) {
        int id = tid + i * 256; int row = id >> 3;
        arow_[i] = row; brow_[i] = row;
        int r = m0 + row;
        aval[i] = (r < M);
        aptr[i] = aval[i] ? (A + (size_t)r * lda + (id & 7) * 4) : A;
        bptr[i] = B + (size_t)(n0 + row) * Kd + (id & 7) * 4;
    }

    float4 ra[4], rb[4];
#pragma unroll
    for (int i = 0; i < 4; i++) {
        ra[i] = aval[i] ? *(const float4*)(aptr[i]) : make_float4(0.f,0.f,0.f,0.f);
        rb[i] = *(const float4*)(bptr[i]);
    }
    auto stage_store = [&](int b) {
#pragma unroll
        for (int i = 0; i < 4; i++) {
            uint4 qa = make_uint4(f2tf(ra[i].x), f2tf(ra[i].y), f2tf(ra[i].z), f2tf(ra[i].w));
            *(uint4*)(sA + b * 4096 + swz(arow_[i], ac) * 4) = qa;
            uint4 qb = make_uint4(f2tf(rb[i].x), f2tf(rb[i].y), f2tf(rb[i].z), f2tf(rb[i].w));
            *(uint4*)(sB + b * 4096 + swz(brow_[i], ac) * 4) = qb;
        }
    };
    stage_store(0);
    __syncthreads();

    float c[2][8][4] = {};
    const int S   = Kd / 32;
    const int sub = lane >> 3, rr = lane & 7;

    for (int s = 0; s < S; s++) {
        if (s + 1 < S) {
#pragma unroll
            for (int i = 0; i < 4; i++) {
                ra[i] = aval[i] ? *(const float4*)(aptr[i] + (s + 1) * 32)
                                : make_float4(0.f,0.f,0.f,0.f);
                rb[i] = *(const float4*)(bptr[i] + (s + 1) * 32);
            }
        }
        const unsigned* tA = sA + (s & 1) * 4096;
        const unsigned* tB = sB + (s & 1) * 4096;
#pragma unroll
        for (int ks = 0; ks < 4; ks++) {
            unsigned a[2][4], bb[8][2];
#pragma unroll
            for (int mt = 0; mt < 2; mt++) {
                int row = wm + mt * 16 + (sub & 1) * 8 + rr;
                int chunk = 2 * ks + (sub >> 1);
                unsigned addr = (unsigned)__cvta_generic_to_shared(tA + swz(row, chunk) * 4);
                ldsm4(a[mt][0], a[mt][1], a[mt][2], a[mt][3], addr);
            }
#pragma unroll
            for (int j = 0; j < 8; j += 2) {
                int row = wn + (j + (sub >> 1)) * 8 + rr;
                int chunk = 2 * ks + (sub & 1);
                unsigned ab = (unsigned)__cvta_generic_to_shared(tB + swz(row, chunk) * 4);
                ldsm4(bb[j][0], bb[j][1], bb[j + 1][0], bb[j + 1][1], ab);
            }
#pragma unroll
            for (int mt = 0; mt < 2; mt++)
#pragma unroll
                for (int nt = 0; nt < 8; nt++)
                    mma8(c[mt][nt], a[mt], bb[nt]);
        }
        if (s + 1 < S) stage_store((s + 1) & 1);
        __syncthreads();
    }

    const int rr2 = lane >> 2, cc = (lane & 3) * 2;
    if (MOE) {
#pragma unroll
        for (int mt = 0; mt < 2; mt++) {
#pragma unroll
            for (int h = 0; h < 2; h++) {
                int r = m0 + wm + mt * 16 + rr2 + h * 8;
                if (r >= M) continue;
                int tok = g_idx[e * T_TOK + r];
                float w  = g_cw[e * T_TOK + r];
                float* orow = out + (size_t)tok * DDIM + n0 + wn;
#pragma unroll
                for (int nt = 0; nt < 8; nt++) {
                    atomicAdd(&orow[nt * 8 + cc + 0], w * c[mt][nt][2 * h + 0]);
                    atomicAdd(&orow[nt * 8 + cc + 1], w * c[mt][nt][2 * h + 1]);
                }
            }
        }
    } else {
#pragma unroll
        for (int mt = 0; mt < 2; mt++) {
#pragma unroll
            for (int h = 0; h < 2; h++) {
                int r = m0 + wm + mt * 16 + rr2 + h * 8;
                float sg = g_sgate[r];
                float* orow = out + (size_t)r * DDIM + n0 + wn;
#pragma unroll
                for (int nt = 0; nt < 8; nt++) {
                    float2 v = make_float2(sg * c[mt][nt][2 * h + 0],
                                           sg * c[mt][nt][2 * h + 1]);
                    *(float2*)(orow + nt * 8 + cc) = v;
                }
            }
        }
    }
}

// ---------------- launch ----------------
extern "C" void kernel_launch(void* const* d_in, const int* in_sizes, int n_in,
                              void* d_out, int out_size) {
    const float* h    = (const float*)d_in[0];  // [T, D]
    const float* gw   = (const float*)d_in[1];  // [E, D]
    const float* gup  = (const float*)d_in[2];  // [E, 2I, D]
    const float* dwn  = (const float*)d_in[3];  // [E, D, I]
    const float* sgw  = (const float*)d_in[4];  // [IS, D]
    const float* suw  = (const float*)d_in[5];  // [IS, D]
    const float* sdw  = (const float*)d_in[6];  // [D, IS]
    const float* segw = (const float*)d_in[7];  // [1, D]
    float* out = (float*)d_out;

    const int SMEM = 65536;
    static bool attr_done = false;
    if (!attr_done) {
        cudaFuncSetAttribute(gemm_gateup_t<true>,  cudaFuncAttributeMaxDynamicSharedMemorySize, SMEM);
        cudaFuncSetAttribute(gemm_gateup_t<false>, cudaFuncAttributeMaxDynamicSharedMemorySize, SMEM);
        cudaFuncSetAttribute(gemm_down_t<true>,    cudaFuncAttributeMaxDynamicSharedMemorySize, SMEM);
        cudaFuncSetAttribute(gemm_down_t<false>,   cudaFuncAttributeMaxDynamicSharedMemorySize, SMEM);
        attr_done = true;
    }

    zero_cnt_kernel<<<1, 32>>>();
    router_kernel<<<T_TOK, 128>>>(h, gw, segw);

    // MoE gate/up (gathered)
    gemm_gateup_t<true><<<dim3(IMOE / 64, T_TOK / 128, NEXP), 256, SMEM>>>(
        h, gup, gup + (long long)IMOE * DDIM, (long long)2 * IMOE * DDIM, DDIM);

    // shared gate/up
    gemm_gateup_t<false><<<dim3(ISH / 64, T_TOK / 128, 1), 256, SMEM>>>(
        h, sgw, suw, 0LL, DDIM);

    // shared down (writes every output element)
    gemm_down_t<false><<<dim3(DDIM / 128, T_TOK / 128, 1), 256, SMEM>>>(
        sdw, 0LL, out, ISH);

    // MoE down (atomic accumulate)
    gemm_down_t<true><<<dim3(DDIM / 128, T_TOK / 128, NEXP), 256, SMEM>>>(
        dwn, (long long)DDIM * IMOE, out, IMOE);
}

// round 4
// speedup vs baseline: 4.5821x; 1.2771x over previous
#include <cuda_runtime.h>
#include <math.h>

#define T_TOK 4096   // B*L tokens
#define DDIM  2048   // hidden dim
#define NEXP  8      // experts
#define IMOE  768    // expert intermediate
#define ISH   4096   // shared expert intermediate

// ---------------- device scratch (static, no allocations) ----------------
__device__ float g_act_shared[(size_t)T_TOK * ISH];            // tf32 bits
__device__ float g_act_moe[(size_t)NEXP * T_TOK * IMOE];       // tf32 bits
__device__ int   g_idx[NEXP * T_TOK];
__device__ float g_cw[NEXP * T_TOK];
__device__ int   g_cnt[NEXP];
__device__ float g_sgate[T_TOK];
// tf32-converted operands
__device__ float g_h_tf[(size_t)T_TOK * DDIM];
__device__ float g_gup_tf[(size_t)NEXP * 2 * IMOE * DDIM];
__device__ float g_dwn_tf[(size_t)NEXP * DDIM * IMOE];
__device__ float g_sgw_tf[(size_t)ISH * DDIM];
__device__ float g_suw_tf[(size_t)ISH * DDIM];
__device__ float g_sdw_tf[(size_t)DDIM * ISH];

// ---------------- helpers ----------------
__device__ __forceinline__ float silu_f(float x) { return x / (1.f + expf(-x)); }

__device__ __forceinline__ unsigned f2tf(float x) {
    unsigned u;
    asm("cvt.rna.tf32.f32 %0, %1;" : "=r"(u) : "f"(x));
    return u;
}
__device__ __forceinline__ void ldsm4(unsigned& r0, unsigned& r1,
                                      unsigned& r2, unsigned& r3, unsigned addr) {
    asm volatile("ldmatrix.sync.aligned.m8n8.x4.shared.b16 {%0,%1,%2,%3}, [%4];"
                 : "=r"(r0), "=r"(r1), "=r"(r2), "=r"(r3) : "r"(addr));
}
__device__ __forceinline__ void mma8(float* c, const unsigned* a, const unsigned* b) {
    asm volatile("mma.sync.aligned.m16n8k8.row.col.f32.tf32.tf32.f32 "
                 "{%0,%1,%2,%3}, {%4,%5,%6,%7}, {%8,%9}, {%0,%1,%2,%3};"
                 : "+f"(c[0]), "+f"(c[1]), "+f"(c[2]), "+f"(c[3])
                 : "r"(a[0]), "r"(a[1]), "r"(a[2]), "r"(a[3]),
                   "r"(b[0]), "r"(b[1]));
}
__device__ __forceinline__ void cp16(unsigned dst, const void* src) {
    asm volatile("cp.async.cg.shared.global [%0], [%1], 16;"
                 :: "r"(dst), "l"(src) : "memory");
}
__device__ __forceinline__ void cp16z(unsigned dst, const void* src, int sz) {
    asm volatile("cp.async.cg.shared.global [%0], [%1], 16, %2;"
                 :: "r"(dst), "l"(src), "r"(sz) : "memory");
}
#define CP_COMMIT() asm volatile("cp.async.commit_group;" ::: "memory")
#define CP_WAIT1()  asm volatile("cp.async.wait_group 1;" ::: "memory")
#define CP_WAIT0()  asm volatile("cp.async.wait_group 0;" ::: "memory")

// XOR-swizzled 16B-chunk index for a [rows x 32-float] k-tile (8 chunks/row)
__device__ __forceinline__ int swz(int row, int chunk) {
    return row * 8 + (chunk ^ (row & 7));
}

// ---------------- small kernels ----------------
__global__ void zero_cnt_kernel() {
    if (threadIdx.x < NEXP) g_cnt[threadIdx.x] = 0;
}

__global__ void router_kernel(const float* __restrict__ h,
                              const float* __restrict__ gate_w,
                              const float* __restrict__ seg_w) {
    int t = blockIdx.x;
    int tid = threadIdx.x;               // 128 threads
    float acc[9];
#pragma unroll
    for (int e = 0; e < 9; e++) acc[e] = 0.f;
    const float* hp = h + (size_t)t * DDIM;
    for (int d = tid; d < DDIM; d += 128) {
        float hv = hp[d];
#pragma unroll
        for (int e = 0; e < 8; e++) acc[e] += hv * gate_w[e * DDIM + d];
        acc[8] += hv * seg_w[d];
    }
#pragma unroll
    for (int e = 0; e < 9; e++) {
#pragma unroll
        for (int off = 16; off > 0; off >>= 1)
            acc[e] += __shfl_down_sync(0xffffffffu, acc[e], off);
    }
    __shared__ float s[9][4];
    int warp = tid >> 5, lane = tid & 31;
    if (lane == 0) {
#pragma unroll
        for (int e = 0; e < 9; e++) s[e][warp] = acc[e];
    }
    __syncthreads();
    if (tid == 0) {
        float logits[9];
#pragma unroll
        for (int e = 0; e < 9; e++)
            logits[e] = s[e][0] + s[e][1] + s[e][2] + s[e][3];
        int i1 = 0; float l1 = logits[0];
#pragma unroll
        for (int e = 1; e < 8; e++)
            if (logits[e] > l1) { l1 = logits[e]; i1 = e; }
        int i2 = -1; float l2 = -3.0e38f;
#pragma unroll
        for (int e = 0; e < 8; e++)
            if (e != i1 && logits[e] > l2) { l2 = logits[e]; i2 = e; }
        float w1 = 1.f / (1.f + expf(l2 - l1));
        float w2 = 1.f - w1;
        int r1 = atomicAdd(&g_cnt[i1], 1);
        g_idx[i1 * T_TOK + r1] = t;  g_cw[i1 * T_TOK + r1] = w1;
        int r2 = atomicAdd(&g_cnt[i2], 1);
        g_idx[i2 * T_TOK + r2] = t;  g_cw[i2 * T_TOK + r2] = w2;
        g_sgate[t] = 1.f / (1.f + expf(-logits[8]));
    }
}

// Convert h + all weights to tf32 bits (rna). blockIdx.y selects tensor.
// Destinations are referenced from device code (valid symbol addresses).
__global__ void cvt_all_kernel(const float* __restrict__ h,
                               const float* __restrict__ gup,
                               const float* __restrict__ dwn,
                               const float* __restrict__ sgw,
                               const float* __restrict__ suw,
                               const float* __restrict__ sdw) {
    const float4* src; float4* dst; size_t n4;
    switch (blockIdx.y) {
        case 0: src=(const float4*)h;   dst=(float4*)g_h_tf;   n4=(size_t)T_TOK*DDIM/4; break;
        case 1: src=(const float4*)gup; dst=(float4*)g_gup_tf; n4=(size_t)NEXP*2*IMOE*DDIM/4; break;
        case 2: src=(const float4*)dwn; dst=(float4*)g_dwn_tf; n4=(size_t)NEXP*DDIM*IMOE/4; break;
        case 3: src=(const float4*)sgw; dst=(float4*)g_sgw_tf; n4=(size_t)ISH*DDIM/4; break;
        case 4: src=(const float4*)suw; dst=(float4*)g_suw_tf; n4=(size_t)ISH*DDIM/4; break;
        default:src=(const float4*)sdw; dst=(float4*)g_sdw_tf; n4=(size_t)DDIM*ISH/4; break;
    }
    size_t i = (size_t)blockIdx.x * blockDim.x + threadIdx.x;
    size_t stride = (size_t)gridDim.x * blockDim.x;
    for (; i < n4; i += stride) {
        float4 v = src[i];
        uint4 q = make_uint4(f2tf(v.x), f2tf(v.y), f2tf(v.z), f2tf(v.w));
        ((uint4*)dst)[i] = q;
    }
}

// ============= fused gate/up GEMM (tf32, cp.async 3-stage pipeline) =============
// Block: 128M x 64N (per matrix). Warps 4(M) x 2(N): warp tile 32x32 per matrix.
// Operands are pre-converted tf32 bits. Output: tf32 bits of silu(g)*u.
// Stage layout: [A: 16KB][G: 8KB][U: 8KB] = 32KB; 3 stages = 96KB.
template<bool GATHER>
__global__ void __launch_bounds__(256, 1)
gemm_gateup_t(const float* __restrict__ A,
              const float* __restrict__ Bg_base,
              const float* __restrict__ Bu_base,
              long long strideB, int Kd)
{
    extern __shared__ unsigned smem[];
    const int e  = blockIdx.z;
    const int M  = GATHER ? g_cnt[e] : T_TOK;
    const int m0 = blockIdx.y * 128;
    if (m0 >= M) return;
    const int n0 = blockIdx.x * 64;

    const float* Bg = Bg_base + (long long)e * strideB;
    const float* Bu = Bu_base + (long long)e * strideB;
    float* C; int ldc;
    if (GATHER) { C = g_act_moe + (long long)e * T_TOK * IMOE; ldc = IMOE; }
    else        { C = g_act_shared;                            ldc = ISH;  }

    const unsigned sbase = (unsigned)__cvta_generic_to_shared(smem);
    const int tid = threadIdx.x, lane = tid & 31, wid = tid >> 5;
    const int wm = (wid & 3) * 32, wn = (wid >> 2) * 32;

    // cp.async source/dst setup
    const float* asrc[4]; int asz[4]; unsigned adst[4];
#pragma unroll
    for (int i = 0; i < 4; i++) {
        int id = tid + i * 256, row = id >> 3, ch = id & 7;
        int r = m0 + row;
        bool v = GATHER ? (r < M) : true;
        asrc[i] = v ? A + (size_t)(GATHER ? g_idx[e * T_TOK + r] : r) * Kd + ch * 4 : A;
        asz[i]  = v ? 16 : 0;
        adst[i] = swz(row, ch) * 16;
    }
    const float* gsrc[2]; const float* usrc[2]; unsigned bdst[2];
#pragma unroll
    for (int i = 0; i < 2; i++) {
        int id = tid + i * 256, row = id >> 3, ch = id & 7;
        gsrc[i] = Bg + (size_t)(n0 + row) * Kd + ch * 4;
        usrc[i] = Bu + (size_t)(n0 + row) * Kd + ch * 4;
        bdst[i] = swz(row, ch) * 16;
    }

    auto issue = [&](int s) {
        unsigned sb = sbase + (s % 3) * 32768;
        int koff = s * 32;
#pragma unroll
        for (int i = 0; i < 4; i++) cp16z(sb + adst[i], asrc[i] + koff, asz[i]);
#pragma unroll
        for (int i = 0; i < 2; i++) cp16(sb + 16384 + bdst[i], gsrc[i] + koff);
#pragma unroll
        for (int i = 0; i < 2; i++) cp16(sb + 24576 + bdst[i], usrc[i] + koff);
    };

    // precomputed fragment offsets
    const int sub = lane >> 3, rr = lane & 7;
    unsigned offA[4][2], offB[4][2];
#pragma unroll
    for (int ks = 0; ks < 4; ks++) {
#pragma unroll
        for (int mt = 0; mt < 2; mt++)
            offA[ks][mt] = swz(wm + mt * 16 + (sub & 1) * 8 + rr, 2 * ks + (sub >> 1)) * 16;
#pragma unroll
        for (int jg = 0; jg < 2; jg++)
            offB[ks][jg] = swz(wn + (jg * 2 + (sub >> 1)) * 8 + rr, 2 * ks + (sub & 1)) * 16;
    }

    float cg[2][4][4] = {}, cu[2][4][4] = {};
    const int S = Kd / 32;

    issue(0); CP_COMMIT();
    issue(1); CP_COMMIT();

#pragma unroll 1
    for (int s = 0; s < S; s++) {
        if (s + 1 < S) { CP_WAIT1(); } else { CP_WAIT0(); }
        __syncthreads();
        unsigned sb = sbase + (s % 3) * 32768;
#pragma unroll
        for (int ks = 0; ks < 4; ks++) {
            unsigned a[2][4], bg[4][2], bu[4][2];
#pragma unroll
            for (int mt = 0; mt < 2; mt++)
                ldsm4(a[mt][0], a[mt][1], a[mt][2], a[mt][3], sb + offA[ks][mt]);
#pragma unroll
            for (int jg = 0; jg < 2; jg++) {
                ldsm4(bg[2*jg][0], bg[2*jg][1], bg[2*jg+1][0], bg[2*jg+1][1],
                      sb + 16384 + offB[ks][jg]);
                ldsm4(bu[2*jg][0], bu[2*jg][1], bu[2*jg+1][0], bu[2*jg+1][1],
                      sb + 24576 + offB[ks][jg]);
            }
#pragma unroll
            for (int mt = 0; mt < 2; mt++)
#pragma unroll
                for (int nt = 0; nt < 4; nt++) {
                    mma8(cg[mt][nt], a[mt], bg[nt]);
                    mma8(cu[mt][nt], a[mt], bu[nt]);
                }
        }
        if (s + 2 < S) { issue(s + 2); CP_COMMIT(); }
    }

    // epilogue: silu(g)*u, stored as tf32 bits for the down GEMM
    const int rr2 = lane >> 2, cc = (lane & 3) * 2;
#pragma unroll
    for (int mt = 0; mt < 2; mt++) {
#pragma unroll
        for (int h2 = 0; h2 < 2; h2++) {
            int r = m0 + wm + mt * 16 + rr2 + h2 * 8;
            if (GATHER && r >= M) continue;
            float* crow = C + (size_t)r * ldc + n0 + wn;
#pragma unroll
            for (int nt = 0; nt < 4; nt++) {
                float v0 = silu_f(cg[mt][nt][2*h2+0]) * cu[mt][nt][2*h2+0];
                float v1 = silu_f(cg[mt][nt][2*h2+1]) * cu[mt][nt][2*h2+1];
                float2 v = make_float2(__uint_as_float(f2tf(v0)),
                                       __uint_as_float(f2tf(v1)));
                *(float2*)(crow + nt * 8 + cc) = v;
            }
        }
    }
}

// ============= down GEMM (tf32, cp.async 3-stage pipeline) =============
// Block: 128M x 64N. Warps 4(M) x 2(N): warp tile 32x32.
// Stage layout: [A: 16KB][B: 8KB] = 24KB; 3 stages = 72KB.
template<bool MOE>
__global__ void __launch_bounds__(256, 1)
gemm_down_t(const float* __restrict__ Bbase, long long strideB,
            float* __restrict__ out, int Kd)
{
    extern __shared__ unsigned smem[];
    const int e  = blockIdx.z;
    const int M  = MOE ? g_cnt[e] : T_TOK;
    const int m0 = blockIdx.y * 128;
    if (m0 >= M) return;
    const int n0 = blockIdx.x * 64;

    const float* A; int lda;
    if (MOE) { A = g_act_moe + (size_t)e * T_TOK * IMOE; lda = IMOE; }
    else     { A = g_act_shared;                         lda = ISH;  }
    const float* B = Bbase + (long long)e * strideB;

    const unsigned sbase = (unsigned)__cvta_generic_to_shared(smem);
    const int tid = threadIdx.x, lane = tid & 31, wid = tid >> 5;
    const int wm = (wid & 3) * 32, wn = (wid >> 2) * 32;

    const float* asrc[4]; int asz[4]; unsigned adst[4];
#pragma unroll
    for (int i = 0; i < 4; i++) {
        int id = tid + i * 256, row = id >> 3, ch = id & 7;
        int r = m0 + row;
        bool v = (r < M);
        asrc[i] = v ? A + (size_t)r * lda + ch * 4 : A;
        asz[i]  = v ? 16 : 0;
        adst[i] = swz(row, ch) * 16;
    }
    const float* bsrc[2]; unsigned bdst[2];
#pragma unroll
    for (int i = 0; i < 2; i++) {
        int id = tid + i * 256, row = id >> 3, ch = id & 7;
        bsrc[i] = B + (size_t)(n0 + row) * Kd + ch * 4;
        bdst[i] = swz(row, ch) * 16;
    }

    auto issue = [&](int s) {
        unsigned sb = sbase + (s % 3) * 24576;
        int koff = s * 32;
#pragma unroll
        for (int i = 0; i < 4; i++) cp16z(sb + adst[i], asrc[i] + koff, asz[i]);
#pragma unroll
        for (int i = 0; i < 2; i++) cp16(sb + 16384 + bdst[i], bsrc[i] + koff);
    };

    const int sub = lane >> 3, rr = lane & 7;
    unsigned offA[4][2], offB[4][2];
#pragma unroll
    for (int ks = 0; ks < 4; ks++) {
#pragma unroll
        for (int mt = 0; mt < 2; mt++)
            offA[ks][mt] = swz(wm + mt * 16 + (sub & 1) * 8 + rr, 2 * ks + (sub >> 1)) * 16;
#pragma unroll
        for (int jg = 0; jg < 2; jg++)
            offB[ks][jg] = swz(wn + (jg * 2 + (sub >> 1)) * 8 + rr, 2 * ks + (sub & 1)) * 16;
    }

    float c[2][4][4] = {};
    const int S = Kd / 32;

    issue(0); CP_COMMIT();
    issue(1); CP_COMMIT();

#pragma unroll 1
    for (int s = 0; s < S; s++) {
        if (s + 1 < S) { CP_WAIT1(); } else { CP_WAIT0(); }
        __syncthreads();
        unsigned sb = sbase + (s % 3) * 24576;
#pragma unroll
        for (int ks = 0; ks < 4; ks++) {
            unsigned a[2][4], bb[4][2];
#pragma unroll
            for (int mt = 0; mt < 2; mt++)
                ldsm4(a[mt][0], a[mt][1], a[mt][2], a[mt][3], sb + offA[ks][mt]);
#pragma unroll
            for (int jg = 0; jg < 2; jg++)
                ldsm4(bb[2*jg][0], bb[2*jg][1], bb[2*jg+1][0], bb[2*jg+1][1],
                      sb + 16384 + offB[ks][jg]);
#pragma unroll
            for (int mt = 0; mt < 2; mt++)
#pragma unroll
                for (int nt = 0; nt < 4; nt++)
                    mma8(c[mt][nt], a[mt], bb[nt]);
        }
        if (s + 2 < S) { issue(s + 2); CP_COMMIT(); }
    }

    const int rr2 = lane >> 2, cc = (lane & 3) * 2;
    if (MOE) {
#pragma unroll
        for (int mt = 0; mt < 2; mt++) {
#pragma unroll
            for (int h2 = 0; h2 < 2; h2++) {
                int r = m0 + wm + mt * 16 + rr2 + h2 * 8;
                if (r >= M) continue;
                int tok = g_idx[e * T_TOK + r];
                float w  = g_cw[e * T_TOK + r];
                float* orow = out + (size_t)tok * DDIM + n0 + wn;
#pragma unroll
                for (int nt = 0; nt < 4; nt++) {
                    atomicAdd(&orow[nt * 8 + cc + 0], w * c[mt][nt][2*h2+0]);
                    atomicAdd(&orow[nt * 8 + cc + 1], w * c[mt][nt][2*h2+1]);
                }
            }
        }
    } else {
#pragma unroll
        for (int mt = 0; mt < 2; mt++) {
#pragma unroll
            for (int h2 = 0; h2 < 2; h2++) {
                int r = m0 + wm + mt * 16 + rr2 + h2 * 8;
                float sg = g_sgate[r];
                float* orow = out + (size_t)r * DDIM + n0 + wn;
#pragma unroll
                for (int nt = 0; nt < 4; nt++) {
                    float2 v = make_float2(sg * c[mt][nt][2*h2+0],
                                           sg * c[mt][nt][2*h2+1]);
                    *(float2*)(orow + nt * 8 + cc) = v;
                }
            }
        }
    }
}

// ---------------- launch ----------------
extern "C" void kernel_launch(void* const* d_in, const int* in_sizes, int n_in,
                              void* d_out, int out_size) {
    const float* h    = (const float*)d_in[0];  // [T, D]
    const float* gw   = (const float*)d_in[1];  // [E, D]
    const float* gup  = (const float*)d_in[2];  // [E, 2I, D]
    const float* dwn  = (const float*)d_in[3];  // [E, D, I]
    const float* sgw  = (const float*)d_in[4];  // [IS, D]
    const float* suw  = (const float*)d_in[5];  // [IS, D]
    const float* sdw  = (const float*)d_in[6];  // [D, IS]
    const float* segw = (const float*)d_in[7];  // [1, D]
    float* out = (float*)d_out;

    const int SMEM_GU = 98304;   // 96KB
    const int SMEM_DN = 73728;   // 72KB

    // DEVICE addresses of __device__ globals (host-side symbol names are
    // shadows — must NOT be passed as kernel args directly).
    static float *p_h_tf, *p_gup_tf, *p_dwn_tf, *p_sgw_tf, *p_suw_tf, *p_sdw_tf;
    static bool init_done = false;
    if (!init_done) {
        cudaFuncSetAttribute(gemm_gateup_t<true>,  cudaFuncAttributeMaxDynamicSharedMemorySize, SMEM_GU);
        cudaFuncSetAttribute(gemm_gateup_t<false>, cudaFuncAttributeMaxDynamicSharedMemorySize, SMEM_GU);
        cudaFuncSetAttribute(gemm_down_t<true>,    cudaFuncAttributeMaxDynamicSharedMemorySize, SMEM_DN);
        cudaFuncSetAttribute(gemm_down_t<false>,   cudaFuncAttributeMaxDynamicSharedMemorySize, SMEM_DN);
        cudaGetSymbolAddress((void**)&p_h_tf,   g_h_tf);
        cudaGetSymbolAddress((void**)&p_gup_tf, g_gup_tf);
        cudaGetSymbolAddress((void**)&p_dwn_tf, g_dwn_tf);
        cudaGetSymbolAddress((void**)&p_sgw_tf, g_sgw_tf);
        cudaGetSymbolAddress((void**)&p_suw_tf, g_suw_tf);
        cudaGetSymbolAddress((void**)&p_sdw_tf, g_sdw_tf);
        init_done = true;
    }

    zero_cnt_kernel<<<1, 32>>>();
    router_kernel<<<T_TOK, 128>>>(h, gw, segw);

    // one-pass tf32 conversion of h + all weights
    cvt_all_kernel<<<dim3(3072, 6), 256>>>(h, gup, dwn, sgw, suw, sdw);

    // MoE gate/up (gathered)
    gemm_gateup_t<true><<<dim3(IMOE / 64, T_TOK / 128, NEXP), 256, SMEM_GU>>>(
        p_h_tf, p_gup_tf, p_gup_tf + (size_t)IMOE * DDIM,
        (long long)2 * IMOE * DDIM, DDIM);

    // shared gate/up
    gemm_gateup_t<false><<<dim3(ISH / 64, T_TOK / 128, 1), 256, SMEM_GU>>>(
        p_h_tf, p_sgw_tf, p_suw_tf, 0LL, DDIM);

    // shared down (writes every output element)
    gemm_down_t<false><<<dim3(DDIM / 64, T_TOK / 128, 1), 256, SMEM_DN>>>(
        p_sdw_tf, 0LL, out, ISH);

    // MoE down (atomic accumulate)
    gemm_down_t<true><<<dim3(DDIM / 64, T_TOK / 128, NEXP), 256, SMEM_DN>>>(
        p_dwn_tf, (long long)DDIM * IMOE, out, IMOE);
}

// round 6
// speedup vs baseline: 5.2909x; 1.1547x over previous
#include <cuda_runtime.h>
#include <math.h>

#define T_TOK 4096   // B*L tokens
#define DDIM  2048   // hidden dim
#define NEXP  8      // experts
#define IMOE  768    // expert intermediate
#define ISH   4096   // shared expert intermediate

// ---------------- device scratch (static, no allocations) ----------------
__device__ float g_act_shared[(size_t)T_TOK * ISH];            // tf32 bits
__device__ float g_act_moe[(size_t)NEXP * T_TOK * IMOE];       // tf32 bits
__device__ int   g_idx[NEXP * T_TOK];
__device__ float g_cw[NEXP * T_TOK];
__device__ int   g_cnt[NEXP];
__device__ float g_sgate[T_TOK];
// tf32-converted operands
__device__ float g_h_tf[(size_t)T_TOK * DDIM];
__device__ float g_gup_tf[(size_t)NEXP * 2 * IMOE * DDIM];
__device__ float g_dwn_tf[(size_t)NEXP * DDIM * IMOE];
__device__ float g_sgw_tf[(size_t)ISH * DDIM];
__device__ float g_suw_tf[(size_t)ISH * DDIM];
__device__ float g_sdw_tf[(size_t)DDIM * ISH];

// ---------------- helpers ----------------
__device__ __forceinline__ float silu_f(float x) { return x / (1.f + expf(-x)); }

__device__ __forceinline__ unsigned f2tf(float x) {
    unsigned u;
    asm("cvt.rna.tf32.f32 %0, %1;" : "=r"(u) : "f"(x));
    return u;
}
__device__ __forceinline__ void ldsm4(unsigned& r0, unsigned& r1,
                                      unsigned& r2, unsigned& r3, unsigned addr) {
    asm volatile("ldmatrix.sync.aligned.m8n8.x4.shared.b16 {%0,%1,%2,%3}, [%4];"
                 : "=r"(r0), "=r"(r1), "=r"(r2), "=r"(r3) : "r"(addr));
}
__device__ __forceinline__ void mma8(float* c, const unsigned* a, const unsigned* b) {
    asm volatile("mma.sync.aligned.m16n8k8.row.col.f32.tf32.tf32.f32 "
                 "{%0,%1,%2,%3}, {%4,%5,%6,%7}, {%8,%9}, {%0,%1,%2,%3};"
                 : "+f"(c[0]), "+f"(c[1]), "+f"(c[2]), "+f"(c[3])
                 : "r"(a[0]), "r"(a[1]), "r"(a[2]), "r"(a[3]),
                   "r"(b[0]), "r"(b[1]));
}
__device__ __forceinline__ void cp16(unsigned dst, const void* src) {
    asm volatile("cp.async.cg.shared.global [%0], [%1], 16;"
                 :: "r"(dst), "l"(src) : "memory");
}
__device__ __forceinline__ void cp16z(unsigned dst, const void* src, int sz) {
    asm volatile("cp.async.cg.shared.global [%0], [%1], 16, %2;"
                 :: "r"(dst), "l"(src), "r"(sz) : "memory");
}
#define CP_COMMIT() asm volatile("cp.async.commit_group;" ::: "memory")
#define CP_WAIT1()  asm volatile("cp.async.wait_group 1;" ::: "memory")
#define CP_WAIT0()  asm volatile("cp.async.wait_group 0;" ::: "memory")

// XOR-swizzled 16B-chunk index for a [rows x 32-float] k-tile (8 chunks/row)
__device__ __forceinline__ int swz(int row, int chunk) {
    return row * 8 + (chunk ^ (row & 7));
}

// ---------------- small kernels ----------------
__global__ void zero_cnt_kernel() {
    if (threadIdx.x < NEXP) g_cnt[threadIdx.x] = 0;
}

__global__ void router_kernel(const float* __restrict__ h,
                              const float* __restrict__ gate_w,
                              const float* __restrict__ seg_w) {
    int t = blockIdx.x;
    int tid = threadIdx.x;               // 128 threads
    float acc[9];
#pragma unroll
    for (int e = 0; e < 9; e++) acc[e] = 0.f;
    const float* hp = h + (size_t)t * DDIM;
    for (int d = tid; d < DDIM; d += 128) {
        float hv = hp[d];
#pragma unroll
        for (int e = 0; e < 8; e++) acc[e] += hv * gate_w[e * DDIM + d];
        acc[8] += hv * seg_w[d];
    }
#pragma unroll
    for (int e = 0; e < 9; e++) {
#pragma unroll
        for (int off = 16; off > 0; off >>= 1)
            acc[e] += __shfl_down_sync(0xffffffffu, acc[e], off);
    }
    __shared__ float s[9][4];
    int warp = tid >> 5, lane = tid & 31;
    if (lane == 0) {
#pragma unroll
        for (int e = 0; e < 9; e++) s[e][warp] = acc[e];
    }
    __syncthreads();
    if (tid == 0) {
        float logits[9];
#pragma unroll
        for (int e = 0; e < 9; e++)
            logits[e] = s[e][0] + s[e][1] + s[e][2] + s[e][3];
        int i1 = 0; float l1 = logits[0];
#pragma unroll
        for (int e = 1; e < 8; e++)
            if (logits[e] > l1) { l1 = logits[e]; i1 = e; }
        int i2 = -1; float l2 = -3.0e38f;
#pragma unroll
        for (int e = 0; e < 8; e++)
            if (e != i1 && logits[e] > l2) { l2 = logits[e]; i2 = e; }
        float w1 = 1.f / (1.f + expf(l2 - l1));
        float w2 = 1.f - w1;
        int r1 = atomicAdd(&g_cnt[i1], 1);
        g_idx[i1 * T_TOK + r1] = t;  g_cw[i1 * T_TOK + r1] = w1;
        int r2 = atomicAdd(&g_cnt[i2], 1);
        g_idx[i2 * T_TOK + r2] = t;  g_cw[i2 * T_TOK + r2] = w2;
        g_sgate[t] = 1.f / (1.f + expf(-logits[8]));
    }
}

// Convert h + all weights to tf32 bits (rna). blockIdx.y selects tensor.
__global__ void cvt_all_kernel(const float* __restrict__ h,
                               const float* __restrict__ gup,
                               const float* __restrict__ dwn,
                               const float* __restrict__ sgw,
                               const float* __restrict__ suw,
                               const float* __restrict__ sdw) {
    const float4* src; float4* dst; size_t n4;
    switch (blockIdx.y) {
        case 0: src=(const float4*)h;   dst=(float4*)g_h_tf;   n4=(size_t)T_TOK*DDIM/4; break;
        case 1: src=(const float4*)gup; dst=(float4*)g_gup_tf; n4=(size_t)NEXP*2*IMOE*DDIM/4; break;
        case 2: src=(const float4*)dwn; dst=(float4*)g_dwn_tf; n4=(size_t)NEXP*DDIM*IMOE/4; break;
        case 3: src=(const float4*)sgw; dst=(float4*)g_sgw_tf; n4=(size_t)ISH*DDIM/4; break;
        case 4: src=(const float4*)suw; dst=(float4*)g_suw_tf; n4=(size_t)ISH*DDIM/4; break;
        default:src=(const float4*)sdw; dst=(float4*)g_sdw_tf; n4=(size_t)DDIM*ISH/4; break;
    }
    size_t i = (size_t)blockIdx.x * blockDim.x + threadIdx.x;
    size_t stride = (size_t)gridDim.x * blockDim.x;
    for (; i < n4; i += stride) {
        float4 v = src[i];
        uint4 q = make_uint4(f2tf(v.x), f2tf(v.y), f2tf(v.z), f2tf(v.w));
        ((uint4*)dst)[i] = q;
    }
}

// ============= fused gate/up GEMM (tf32, cp.async 3-stage, 2 CTAs/SM) =============
// Block: 128M x 64N (per matrix). Warps 4(M) x 2(N): warp tile 32x32 per matrix.
// Stage layout: [A: 16KB][G: 8KB][U: 8KB] = 32KB; 3 stages = 96KB.
template<bool GATHER>
__global__ void __launch_bounds__(256, 2)
gemm_gateup_t(const float* __restrict__ A,
              const float* __restrict__ Bg_base,
              const float* __restrict__ Bu_base,
              long long strideB, int Kd)
{
    extern __shared__ unsigned smem[];
    const int e  = blockIdx.z;
    const int M  = GATHER ? g_cnt[e] : T_TOK;
    const int m0 = blockIdx.y * 128;
    if (m0 >= M) return;
    const int n0 = blockIdx.x * 64;

    const float* Bg = Bg_base + (long long)e * strideB;
    const float* Bu = Bu_base + (long long)e * strideB;
    float* C; int ldc;
    if (GATHER) { C = g_act_moe + (long long)e * T_TOK * IMOE; ldc = IMOE; }
    else        { C = g_act_shared;                            ldc = ISH;  }

    const unsigned sbase = (unsigned)__cvta_generic_to_shared(smem);
    const int tid = threadIdx.x, lane = tid & 31, wid = tid >> 5;
    const int wm = (wid & 3) * 32, wn = (wid >> 2) * 32;

    // cp.async source/dst setup
    const float* asrc[4]; int asz[4]; unsigned adst[4];
#pragma unroll
    for (int i = 0; i < 4; i++) {
        int id = tid + i * 256, row = id >> 3, ch = id & 7;
        int r = m0 + row;
        bool v = GATHER ? (r < M) : true;
        asrc[i] = v ? A + (size_t)(GATHER ? g_idx[e * T_TOK + r] : r) * Kd + ch * 4 : A;
        asz[i]  = v ? 16 : 0;
        adst[i] = swz(row, ch) * 16;
    }
    const float* gsrc[2]; const float* usrc[2]; unsigned bdst[2];
#pragma unroll
    for (int i = 0; i < 2; i++) {
        int id = tid + i * 256, row = id >> 3, ch = id & 7;
        gsrc[i] = Bg + (size_t)(n0 + row) * Kd + ch * 4;
        usrc[i] = Bu + (size_t)(n0 + row) * Kd + ch * 4;
        bdst[i] = swz(row, ch) * 16;
    }

    auto issue = [&](int s) {
        unsigned sb = sbase + (s % 3) * 32768;
        int koff = s * 32;
#pragma unroll
        for (int i = 0; i < 4; i++) cp16z(sb + adst[i], asrc[i] + koff, asz[i]);
#pragma unroll
        for (int i = 0; i < 2; i++) cp16(sb + 16384 + bdst[i], gsrc[i] + koff);
#pragma unroll
        for (int i = 0; i < 2; i++) cp16(sb + 24576 + bdst[i], usrc[i] + koff);
    };

    // precomputed fragment offsets
    const int sub = lane >> 3, rr = lane & 7;
    unsigned offA[4][2], offB[4][2];
#pragma unroll
    for (int ks = 0; ks < 4; ks++) {
#pragma unroll
        for (int mt = 0; mt < 2; mt++)
            offA[ks][mt] = swz(wm + mt * 16 + (sub & 1) * 8 + rr, 2 * ks + (sub >> 1)) * 16;
#pragma unroll
        for (int jg = 0; jg < 2; jg++)
            offB[ks][jg] = swz(wn + (jg * 2 + (sub >> 1)) * 8 + rr, 2 * ks + (sub & 1)) * 16;
    }

    float cg[2][4][4] = {}, cu[2][4][4] = {};
    const int S = Kd / 32;

    issue(0); CP_COMMIT();
    issue(1); CP_COMMIT();

#pragma unroll 1
    for (int s = 0; s < S; s++) {
        if (s + 1 < S) { CP_WAIT1(); } else { CP_WAIT0(); }
        __syncthreads();
        unsigned sb = sbase + (s % 3) * 32768;
#pragma unroll
        for (int ks = 0; ks < 4; ks++) {
            unsigned a[2][4], bg[4][2], bu[4][2];
#pragma unroll
            for (int mt = 0; mt < 2; mt++)
                ldsm4(a[mt][0], a[mt][1], a[mt][2], a[mt][3], sb + offA[ks][mt]);
#pragma unroll
            for (int jg = 0; jg < 2; jg++) {
                ldsm4(bg[2*jg][0], bg[2*jg][1], bg[2*jg+1][0], bg[2*jg+1][1],
                      sb + 16384 + offB[ks][jg]);
                ldsm4(bu[2*jg][0], bu[2*jg][1], bu[2*jg+1][0], bu[2*jg+1][1],
                      sb + 24576 + offB[ks][jg]);
            }
#pragma unroll
            for (int mt = 0; mt < 2; mt++)
#pragma unroll
                for (int nt = 0; nt < 4; nt++) {
                    mma8(cg[mt][nt], a[mt], bg[nt]);
                    mma8(cu[mt][nt], a[mt], bu[nt]);
                }
        }
        if (s + 2 < S) { issue(s + 2); CP_COMMIT(); }
    }

    // epilogue: silu(g)*u, stored as tf32 bits for the down GEMM
    const int rr2 = lane >> 2, cc = (lane & 3) * 2;
#pragma unroll
    for (int mt = 0; mt < 2; mt++) {
#pragma unroll
        for (int h2 = 0; h2 < 2; h2++) {
            int r = m0 + wm + mt * 16 + rr2 + h2 * 8;
            if (GATHER && r >= M) continue;
            float* crow = C + (size_t)r * ldc + n0 + wn;
#pragma unroll
            for (int nt = 0; nt < 4; nt++) {
                float v0 = silu_f(cg[mt][nt][2*h2+0]) * cu[mt][nt][2*h2+0];
                float v1 = silu_f(cg[mt][nt][2*h2+1]) * cu[mt][nt][2*h2+1];
                float2 v = make_float2(__uint_as_float(f2tf(v0)),
                                       __uint_as_float(f2tf(v1)));
                *(float2*)(crow + nt * 8 + cc) = v;
            }
        }
    }
}

// ============= down GEMM (tf32, cp.async 3-stage, 2 CTAs/SM) =============
// Block: 128M x 64N. Warps 4(M) x 2(N): warp tile 32x32.
// Stage layout: [A: 16KB][B: 8KB] = 24KB; 3 stages = 72KB.
template<bool MOE>
__global__ void __launch_bounds__(256, 2)
gemm_down_t(const float* __restrict__ Bbase, long long strideB,
            float* __restrict__ out, int Kd)
{
    extern __shared__ unsigned smem[];
    const int e  = blockIdx.z;
    const int M  = MOE ? g_cnt[e] : T_TOK;
    const int m0 = blockIdx.y * 128;
    if (m0 >= M) return;
    const int n0 = blockIdx.x * 64;

    const float* A; int lda;
    if (MOE) { A = g_act_moe + (size_t)e * T_TOK * IMOE; lda = IMOE; }
    else     { A = g_act_shared;                         lda = ISH;  }
    const float* B = Bbase + (long long)e * strideB;

    const unsigned sbase = (unsigned)__cvta_generic_to_shared(smem);
    const int tid = threadIdx.x, lane = tid & 31, wid = tid >> 5;
    const int wm = (wid & 3) * 32, wn = (wid >> 2) * 32;

    const float* asrc[4]; int asz[4]; unsigned adst[4];
#pragma unroll
    for (int i = 0; i < 4; i++) {
        int id = tid + i * 256, row = id >> 3, ch = id & 7;
        int r = m0 + row;
        bool v = (r < M);
        asrc[i] = v ? A + (size_t)r * lda + ch * 4 : A;
        asz[i]  = v ? 16 : 0;
        adst[i] = swz(row, ch) * 16;
    }
    const float* bsrc[2]; unsigned bdst[2];
#pragma unroll
    for (int i = 0; i < 2; i++) {
        int id = tid + i * 256, row = id >> 3, ch = id & 7;
        bsrc[i] = B + (size_t)(n0 + row) * Kd + ch * 4;
        bdst[i] = swz(row, ch) * 16;
    }

    auto issue = [&](int s) {
        unsigned sb = sbase + (s % 3) * 24576;
        int koff = s * 32;
#pragma unroll
        for (int i = 0; i < 4; i++) cp16z(sb + adst[i], asrc[i] + koff, asz[i]);
#pragma unroll
        for (int i = 0; i < 2; i++) cp16(sb + 16384 + bdst[i], bsrc[i] + koff);
    };

    const int sub = lane >> 3, rr = lane & 7;
    unsigned offA[4][2], offB[4][2];
#pragma unroll
    for (int ks = 0; ks < 4; ks++) {
#pragma unroll
        for (int mt = 0; mt < 2; mt++)
            offA[ks][mt] = swz(wm + mt * 16 + (sub & 1) * 8 + rr, 2 * ks + (sub >> 1)) * 16;
#pragma unroll
        for (int jg = 0; jg < 2; jg++)
            offB[ks][jg] = swz(wn + (jg * 2 + (sub >> 1)) * 8 + rr, 2 * ks + (sub & 1)) * 16;
    }

    float c[2][4][4] = {};
    const int S = Kd / 32;

    issue(0); CP_COMMIT();
    issue(1); CP_COMMIT();

#pragma unroll 1
    for (int s = 0; s < S; s++) {
        if (s + 1 < S) { CP_WAIT1(); } else { CP_WAIT0(); }
        __syncthreads();
        unsigned sb = sbase + (s % 3) * 24576;
#pragma unroll
        for (int ks = 0; ks < 4; ks++) {
            unsigned a[2][4], bb[4][2];
#pragma unroll
            for (int mt = 0; mt < 2; mt++)
                ldsm4(a[mt][0], a[mt][1], a[mt][2], a[mt][3], sb + offA[ks][mt]);
#pragma unroll
            for (int jg = 0; jg < 2; jg++)
                ldsm4(bb[2*jg][0], bb[2*jg][1], bb[2*jg+1][0], bb[2*jg+1][1],
                      sb + 16384 + offB[ks][jg]);
#pragma unroll
            for (int mt = 0; mt < 2; mt++)
#pragma unroll
                for (int nt = 0; nt < 4; nt++)
                    mma8(c[mt][nt], a[mt], bb[nt]);
        }
        if (s + 2 < S) { issue(s + 2); CP_COMMIT(); }
    }

    const int rr2 = lane >> 2, cc = (lane & 3) * 2;
    if (MOE) {
#pragma unroll
        for (int mt = 0; mt < 2; mt++) {
#pragma unroll
            for (int h2 = 0; h2 < 2; h2++) {
                int r = m0 + wm + mt * 16 + rr2 + h2 * 8;
                if (r >= M) continue;
                int tok = g_idx[e * T_TOK + r];
                float w  = g_cw[e * T_TOK + r];
                float* orow = out + (size_t)tok * DDIM + n0 + wn;
#pragma unroll
                for (int nt = 0; nt < 4; nt++) {
                    atomicAdd(&orow[nt * 8 + cc + 0], w * c[mt][nt][2*h2+0]);
                    atomicAdd(&orow[nt * 8 + cc + 1], w * c[mt][nt][2*h2+1]);
                }
            }
        }
    } else {
#pragma unroll
        for (int mt = 0; mt < 2; mt++) {
#pragma unroll
            for (int h2 = 0; h2 < 2; h2++) {
                int r = m0 + wm + mt * 16 + rr2 + h2 * 8;
                float sg = g_sgate[r];
                float* orow = out + (size_t)r * DDIM + n0 + wn;
#pragma unroll
                for (int nt = 0; nt < 4; nt++) {
                    float2 v = make_float2(sg * c[mt][nt][2*h2+0],
                                           sg * c[mt][nt][2*h2+1]);
                    *(float2*)(orow + nt * 8 + cc) = v;
                }
            }
        }
    }
}

// ---------------- launch ----------------
extern "C" void kernel_launch(void* const* d_in, const int* in_sizes, int n_in,
                              void* d_out, int out_size) {
    const float* h    = (const float*)d_in[0];  // [T, D]
    const float* gw   = (const float*)d_in[1];  // [E, D]
    const float* gup  = (const float*)d_in[2];  // [E, 2I, D]
    const float* dwn  = (const float*)d_in[3];  // [E, D, I]
    const float* sgw  = (const float*)d_in[4];  // [IS, D]
    const float* suw  = (const float*)d_in[5];  // [IS, D]
    const float* sdw  = (const float*)d_in[6];  // [D, IS]
    const float* segw = (const float*)d_in[7];  // [1, D]
    float* out = (float*)d_out;

    const int SMEM_GU = 98304;   // 96KB (3 stages x 32KB); 2 CTAs/SM = 192KB <= 228KB
    const int SMEM_DN = 73728;   // 72KB (3 stages x 24KB); 2 CTAs/SM = 144KB

    // DEVICE addresses of __device__ globals (host-side names are shadow symbols)
    static float *p_h_tf, *p_gup_tf, *p_dwn_tf, *p_sgw_tf, *p_suw_tf, *p_sdw_tf;
    static bool init_done = false;
    if (!init_done) {
        cudaFuncSetAttribute(gemm_gateup_t<true>,  cudaFuncAttributeMaxDynamicSharedMemorySize, SMEM_GU);
        cudaFuncSetAttribute(gemm_gateup_t<false>, cudaFuncAttributeMaxDynamicSharedMemorySize, SMEM_GU);
        cudaFuncSetAttribute(gemm_down_t<true>,    cudaFuncAttributeMaxDynamicSharedMemorySize, SMEM_DN);
        cudaFuncSetAttribute(gemm_down_t<false>,   cudaFuncAttributeMaxDynamicSharedMemorySize, SMEM_DN);
        cudaGetSymbolAddress((void**)&p_h_tf,   g_h_tf);
        cudaGetSymbolAddress((void**)&p_gup_tf, g_gup_tf);
        cudaGetSymbolAddress((void**)&p_dwn_tf, g_dwn_tf);
        cudaGetSymbolAddress((void**)&p_sgw_tf, g_sgw_tf);
        cudaGetSymbolAddress((void**)&p_suw_tf, g_suw_tf);
        cudaGetSymbolAddress((void**)&p_sdw_tf, g_sdw_tf);
        init_done = true;
    }

    zero_cnt_kernel<<<1, 32>>>();
    router_kernel<<<T_TOK, 128>>>(h, gw, segw);

    // one-pass tf32 conversion of h + all weights
    cvt_all_kernel<<<dim3(3072, 6), 256>>>(h, gup, dwn, sgw, suw, sdw);

    // MoE gate/up (gathered)
    gemm_gateup_t<true><<<dim3(IMOE / 64, T_TOK / 128, NEXP), 256, SMEM_GU>>>(
        p_h_tf, p_gup_tf, p_gup_tf + (size_t)IMOE * DDIM,
        (long long)2 * IMOE * DDIM, DDIM);

    // shared gate/up
    gemm_gateup_t<false><<<dim3(ISH / 64, T_TOK / 128, 1), 256, SMEM_GU>>>(
        p_h_tf, p_sgw_tf, p_suw_tf, 0LL, DDIM);

    // shared down (writes every output element)
    gemm_down_t<false><<<dim3(DDIM / 64, T_TOK / 128, 1), 256, SMEM_DN>>>(
        p_sdw_tf, 0LL, out, ISH);

    // MoE down (atomic accumulate)
    gemm_down_t<true><<<dim3(DDIM / 64, T_TOK / 128, NEXP), 256, SMEM_DN>>>(
        p_dwn_tf, (long long)DDIM * IMOE, out, IMOE);
}